// round 2
// baseline (speedup 1.0000x reference)
#include <cuda_runtime.h>
#include <math.h>
#include <stdint.h>

#define BB 2
#define SS 2048
#define DD 1024
#define HH 16
#define HD 64

// -------- scratch (allocation-free: __device__ globals) --------
__device__ float g_Q[BB*SS*DD];
__device__ float g_K[BB*SS*DD];
__device__ float g_V[BB*SS*DD];
__device__ float g_att[BB*SS*DD];

// ======================================================================
// GEMM: C[M,N] = A[M,K] * B[N,K]^T  (+ optional bias[N])
// 64x64 block tile, 16x16 threads, 4x4 register tile, KTILE=32
// float4 global loads; smem row pad = 36 floats (16B-aligned rows)
// ======================================================================
__global__ __launch_bounds__(256) void gemm_xt_kernel(
    const float* __restrict__ A, const float* __restrict__ Bw,
    const float* __restrict__ bias, float* __restrict__ C,
    int M, int N, int K)
{
    __shared__ float as[64][36];
    __shared__ float bs[64][36];

    const int tid = threadIdx.x;
    const int tx = tid & 15;
    const int ty = tid >> 4;
    const int m0 = blockIdx.y * 64;
    const int n0 = blockIdx.x * 64;

    // tile load mapping: 64 rows x 32 cols = 512 float4s; 256 threads x 2
    const int lr = tid >> 3;          // 0..31 (row pair base)
    const int lc = (tid & 7) * 4;     // 0..28 step 4

    float acc[4][4] = {};

    for (int kt = 0; kt < K; kt += 32) {
        #pragma unroll
        for (int i = 0; i < 2; i++) {
            int r = lr + i * 32;
            float4 va = *(const float4*)&A[(size_t)(m0 + r) * K + kt + lc];
            float4 vb = *(const float4*)&Bw[(size_t)(n0 + r) * K + kt + lc];
            *(float4*)&as[r][lc] = va;
            *(float4*)&bs[r][lc] = vb;
        }
        __syncthreads();

        #pragma unroll
        for (int k = 0; k < 32; k++) {
            float a[4], b[4];
            #pragma unroll
            for (int r = 0; r < 4; r++) a[r] = as[ty * 4 + r][k];
            #pragma unroll
            for (int c = 0; c < 4; c++) b[c] = bs[tx * 4 + c][k];
            #pragma unroll
            for (int r = 0; r < 4; r++)
                #pragma unroll
                for (int c = 0; c < 4; c++)
                    acc[r][c] = fmaf(a[r], b[c], acc[r][c]);
        }
        __syncthreads();
    }

    #pragma unroll
    for (int r = 0; r < 4; r++) {
        #pragma unroll
        for (int c = 0; c < 4; c++) {
            float v = acc[r][c];
            if (bias) v += bias[n0 + tx * 4 + c];
            C[(size_t)(m0 + ty * 4 + r) * N + n0 + tx * 4 + c] = v;
        }
    }
}

// ======================================================================
// Flash attention (fp32, online softmax).
// Q,K,V,O in (B,S,D) layout with D = H*HD; each block handles one (b,h)
// and 64 query rows. Key/value tiles of 64 rows streamed from gmem.
// ======================================================================
// dynamic smem layout (floats), row stride 68 (16B-aligned, conflict-free):
//   qs   [64][68]  @ 0      (4352)
//   ks   [64][68]  @ 4352   (4352)
//   vs   [64][68]  @ 8704   (4352)
//   ps   [64][68]  @ 13056  (4352)
//   part [64][17]  @ 17408  (1088)
//   mrow [64]      @ 18496
//   lrow [64]      @ 18560
//   crow [64]      @ 18624
// total = 18688 floats = 74752 bytes
#define FLASH_SMEM_BYTES (18688 * 4)

__global__ __launch_bounds__(256) void flash_attn_kernel(
    const float* __restrict__ Q, const float* __restrict__ Kp,
    const float* __restrict__ Vp, float* __restrict__ O)
{
    extern __shared__ float sm[];
    float* qs   = sm;
    float* ks   = sm + 4352;
    float* vs   = sm + 8704;
    float* ps   = sm + 13056;
    float* part = sm + 17408;
    float* mrow = sm + 18496;
    float* lrow = sm + 18560;
    float* crow = sm + 18624;

    const int tid = threadIdx.x;
    const int tx = tid & 15;
    const int ty = tid >> 4;
    const int bh = blockIdx.y;
    const int b = bh >> 4;
    const int h = bh & 15;
    const int q0 = blockIdx.x * 64;
    const float scale = 0.03125f; // 1/sqrt(1024)

    // tile load mapping: 64 rows x 64 cols = 1024 float4s; 256 threads x 4
    const int fr = tid >> 4;          // 0..15 row base
    const int fc = (tid & 15) * 4;    // 0..60 step 4

    // load Q tile (64 rows x 64 dims)
    const float* qbase = Q + ((size_t)(b * SS + q0)) * DD + h * HD;
    #pragma unroll
    for (int i = 0; i < 4; i++) {
        int r = fr + i * 16;
        *(float4*)&qs[r * 68 + fc] = *(const float4*)&qbase[(size_t)r * DD + fc];
    }
    if (tid < 64) {
        mrow[tid] = -INFINITY;
        lrow[tid] = 0.0f;
    }
    float oacc[4][4] = {};
    __syncthreads();

    for (int kb = 0; kb < SS / 64; kb++) {
        const float* kbase = Kp + ((size_t)(b * SS + kb * 64)) * DD + h * HD;
        const float* vbase = Vp + ((size_t)(b * SS + kb * 64)) * DD + h * HD;
        #pragma unroll
        for (int i = 0; i < 4; i++) {
            int r = fr + i * 16;
            *(float4*)&ks[r * 68 + fc] = *(const float4*)&kbase[(size_t)r * DD + fc];
            *(float4*)&vs[r * 68 + fc] = *(const float4*)&vbase[(size_t)r * DD + fc];
        }
        __syncthreads();                                   // (1)

        // scores: s[r][c] = q(4ty+r) . k(4tx+c)
        float s[4][4] = {};
        #pragma unroll 8
        for (int d = 0; d < 64; d++) {
            float a[4], bb[4];
            #pragma unroll
            for (int r = 0; r < 4; r++) a[r] = qs[(ty * 4 + r) * 68 + d];
            #pragma unroll
            for (int c = 0; c < 4; c++) bb[c] = ks[(tx * 4 + c) * 68 + d];
            #pragma unroll
            for (int r = 0; r < 4; r++)
                #pragma unroll
                for (int c = 0; c < 4; c++)
                    s[r][c] = fmaf(a[r], bb[c], s[r][c]);
        }

        // scale + per-thread row max
        #pragma unroll
        for (int r = 0; r < 4; r++) {
            float pm = -INFINITY;
            #pragma unroll
            for (int c = 0; c < 4; c++) {
                s[r][c] *= scale;
                pm = fmaxf(pm, s[r][c]);
            }
            part[(ty * 4 + r) * 17 + tx] = pm;
        }
        __syncthreads();                                   // (2)

        if (tid < 64) {
            float mx = part[tid * 17];
            #pragma unroll
            for (int j = 1; j < 16; j++) mx = fmaxf(mx, part[tid * 17 + j]);
            float mnew = fmaxf(mrow[tid], mx);
            crow[tid] = __expf(mrow[tid] - mnew);
            mrow[tid] = mnew;
        }
        __syncthreads();                                   // (3)

        // p = exp(s - m); rescale oacc; stage p to smem; partial row sums
        #pragma unroll
        for (int r = 0; r < 4; r++) {
            const int row = ty * 4 + r;
            const float mr = mrow[row];
            const float cr = crow[row];
            float psum = 0.0f;
            #pragma unroll
            for (int c = 0; c < 4; c++) {
                float p = __expf(s[r][c] - mr);
                ps[row * 68 + tx * 4 + c] = p;
                psum += p;
                oacc[r][c] *= cr;
            }
            part[row * 17 + tx] = psum;
        }
        __syncthreads();                                   // (4)

        if (tid < 64) {
            float ssum = 0.0f;
            #pragma unroll
            for (int j = 0; j < 16; j++) ssum += part[tid * 17 + j];
            lrow[tid] = lrow[tid] * crow[tid] + ssum;
        }

        // oacc += P * V  (over the 64 keys of this block)
        #pragma unroll 8
        for (int j = 0; j < 64; j++) {
            float pv[4], vv[4];
            #pragma unroll
            for (int r = 0; r < 4; r++) pv[r] = ps[(ty * 4 + r) * 68 + j];
            #pragma unroll
            for (int c = 0; c < 4; c++) vv[c] = vs[j * 68 + tx * 4 + c];
            #pragma unroll
            for (int r = 0; r < 4; r++)
                #pragma unroll
                for (int c = 0; c < 4; c++)
                    oacc[r][c] = fmaf(pv[r], vv[c], oacc[r][c]);
        }
        __syncthreads();                                   // (5)
    }

    // epilogue: normalize and write (B,S,D) layout
    float* obase = O + ((size_t)(b * SS + q0)) * DD + h * HD;
    #pragma unroll
    for (int r = 0; r < 4; r++) {
        const float inv_l = 1.0f / lrow[ty * 4 + r];
        #pragma unroll
        for (int c = 0; c < 4; c++) {
            obase[(size_t)(ty * 4 + r) * DD + tx * 4 + c] = oacc[r][c] * inv_l;
        }
    }
}

// ======================================================================
// launch
// ======================================================================
extern "C" void kernel_launch(void* const* d_in, const int* in_sizes, int n_in,
                              void* d_out, int out_size)
{
    const float* queries = (const float*)d_in[0];
    const float* keys    = (const float*)d_in[1];
    const float* values  = (const float*)d_in[2];
    const float* Wq      = (const float*)d_in[3];
    const float* Wk      = (const float*)d_in[4];
    const float* Wv      = (const float*)d_in[5];
    const float* Wo      = (const float*)d_in[6];
    const float* bo      = (const float*)d_in[7];
    float* out = (float*)d_out;

    float *gQ, *gK, *gV, *gA;
    cudaGetSymbolAddress((void**)&gQ, g_Q);
    cudaGetSymbolAddress((void**)&gK, g_K);
    cudaGetSymbolAddress((void**)&gV, g_V);
    cudaGetSymbolAddress((void**)&gA, g_att);

    cudaFuncSetAttribute(flash_attn_kernel,
                         cudaFuncAttributeMaxDynamicSharedMemorySize,
                         FLASH_SMEM_BYTES);

    const int M = BB * SS;   // 4096
    const int N = DD;        // 1024
    const int K = DD;        // 1024
    dim3 gemm_grid(N / 64, M / 64);   // (16, 64)
    dim3 gemm_block(256);

    // Q/K/V projections: X @ W^T
    gemm_xt_kernel<<<gemm_grid, gemm_block>>>(queries, Wq, nullptr, gQ, M, N, K);
    gemm_xt_kernel<<<gemm_grid, gemm_block>>>(keys,    Wk, nullptr, gK, M, N, K);
    gemm_xt_kernel<<<gemm_grid, gemm_block>>>(values,  Wv, nullptr, gV, M, N, K);

    // attention
    dim3 fl_grid(SS / 64, BB * HH);   // (32, 32)
    flash_attn_kernel<<<fl_grid, 256, FLASH_SMEM_BYTES>>>(gQ, gK, gV, gA);

    // output projection + bias
    gemm_xt_kernel<<<gemm_grid, gemm_block>>>(gA, Wo, bo, out, M, N, K);
}

// round 4
// speedup vs baseline: 5.6830x; 5.6830x over previous
#include <cuda_runtime.h>
#include <math.h>
#include <stdint.h>

#define BB 2
#define SS 2048
#define DD 1024
#define HH 16
#define HD 64

// -------- scratch (allocation-free: __device__ globals) --------
__device__ float g_Q[BB*SS*DD];
__device__ float g_K[BB*SS*DD];
__device__ float g_V[BB*SS*DD];
__device__ float g_att[BB*SS*DD];

// -------- tf32 helpers --------
__device__ __forceinline__ uint32_t f2tf32(float x) {
    uint32_t r;
    asm("cvt.rna.tf32.f32 %0, %1;" : "=r"(r) : "f"(x));
    return r;
}

// D += A(16x8) * B(8x8), tf32 inputs, fp32 accum
__device__ __forceinline__ void mma_tf32(float* d, const uint32_t* a, const uint32_t* b) {
    asm volatile(
        "mma.sync.aligned.m16n8k8.row.col.f32.tf32.tf32.f32 "
        "{%0,%1,%2,%3},{%4,%5,%6,%7},{%8,%9},{%0,%1,%2,%3};"
        : "+f"(d[0]), "+f"(d[1]), "+f"(d[2]), "+f"(d[3])
        : "r"(a[0]), "r"(a[1]), "r"(a[2]), "r"(a[3]), "r"(b[0]), "r"(b[1]));
}

// ======================================================================
// GEMM: C[M,N] = A[M,K] * B[N,K]^T (+ optional bias[N]), tf32 tensor core
// 128x128 block tile, 256 threads (8 warps, 2Mx4N), 64x32 warp tile, KT=32
// ======================================================================
__global__ __launch_bounds__(256) void gemm_tf32_kernel(
    const float* __restrict__ A, const float* __restrict__ Bw,
    const float* __restrict__ bias, float* __restrict__ C,
    int M, int N, int K)
{
    __shared__ uint32_t As[128 * 36];
    __shared__ uint32_t Bs[128 * 36];

    const int tid  = threadIdx.x;
    const int lane = tid & 31;
    const int w    = tid >> 5;
    const int wm   = w & 1;        // 0..1 -> 64 rows each
    const int wn   = w >> 1;       // 0..3 -> 32 cols each
    const int lr   = lane >> 2;    // 0..7
    const int lc   = lane & 3;     // 0..3

    const int m0 = blockIdx.y * 128;
    const int n0 = blockIdx.x * 128;

    const int lr2 = tid >> 3;         // 0..31
    const int lc2 = (tid & 7) * 4;    // 0..28

    float acc[4][4][4];
    #pragma unroll
    for (int i = 0; i < 4; i++)
        #pragma unroll
        for (int j = 0; j < 4; j++)
            #pragma unroll
            for (int t = 0; t < 4; t++) acc[i][j][t] = 0.0f;

    for (int kt = 0; kt < K; kt += 32) {
        #pragma unroll
        for (int i = 0; i < 4; i++) {
            int r = lr2 + i * 32;
            float4 va = *(const float4*)&A[(size_t)(m0 + r) * K + kt + lc2];
            float4 vb = *(const float4*)&Bw[(size_t)(n0 + r) * K + kt + lc2];
            uint4 ua = { f2tf32(va.x), f2tf32(va.y), f2tf32(va.z), f2tf32(va.w) };
            uint4 ub = { f2tf32(vb.x), f2tf32(vb.y), f2tf32(vb.z), f2tf32(vb.w) };
            *(uint4*)&As[r * 36 + lc2] = ua;
            *(uint4*)&Bs[r * 36 + lc2] = ub;
        }
        __syncthreads();

        #pragma unroll
        for (int ks = 0; ks < 4; ks++) {
            const int kk = ks * 8;
            uint32_t af[4][4];
            #pragma unroll
            for (int mf = 0; mf < 4; mf++) {
                int r = wm * 64 + mf * 16 + lr;
                af[mf][0] = As[r * 36 + kk + lc];
                af[mf][1] = As[(r + 8) * 36 + kk + lc];
                af[mf][2] = As[r * 36 + kk + lc + 4];
                af[mf][3] = As[(r + 8) * 36 + kk + lc + 4];
            }
            uint32_t bf[4][2];
            #pragma unroll
            for (int nf = 0; nf < 4; nf++) {
                int n = wn * 32 + nf * 8 + lr;
                bf[nf][0] = Bs[n * 36 + kk + lc];
                bf[nf][1] = Bs[n * 36 + kk + lc + 4];
            }
            #pragma unroll
            for (int mf = 0; mf < 4; mf++)
                #pragma unroll
                for (int nf = 0; nf < 4; nf++)
                    mma_tf32(acc[mf][nf], af[mf], bf[nf]);
        }
        __syncthreads();
    }

    // epilogue
    #pragma unroll
    for (int mf = 0; mf < 4; mf++) {
        int r = m0 + wm * 64 + mf * 16 + lr;
        #pragma unroll
        for (int nf = 0; nf < 4; nf++) {
            int c = n0 + wn * 32 + nf * 8 + 2 * lc;
            float b0 = 0.0f, b1 = 0.0f;
            if (bias) { b0 = bias[c]; b1 = bias[c + 1]; }
            float2 v0 = { acc[mf][nf][0] + b0, acc[mf][nf][1] + b1 };
            float2 v1 = { acc[mf][nf][2] + b0, acc[mf][nf][3] + b1 };
            *(float2*)&C[(size_t)r * N + c] = v0;
            *(float2*)&C[(size_t)(r + 8) * N + c] = v1;
        }
    }
}

// ======================================================================
// Flash attention, tf32 tensor core. 64 q-rows/block, one (b,h)/block.
// 128 threads (4 warps, 2Mx2N). Online softmax with register-replicated
// m/l state. P staged via smem (tf32) for C->A fragment conversion.
// smem (floats, stride 72):
//   qs 64x72 @0, ks @4608, vs @9216, ps @13824,
//   redmax 64x2 @18432, rowsum 64x2 @18560   -> total 18688 floats
// ======================================================================
#define FL_SMEM_FLOATS 18688
#define FL_SMEM_BYTES (FL_SMEM_FLOATS * 4)

__global__ __launch_bounds__(128) void flash_tf32_kernel(
    const float* __restrict__ Q, const float* __restrict__ Kp,
    const float* __restrict__ Vp, float* __restrict__ O)
{
    extern __shared__ float smf[];
    uint32_t* qs = (uint32_t*)smf;
    uint32_t* ks = (uint32_t*)(smf + 4608);
    uint32_t* vs = (uint32_t*)(smf + 9216);
    uint32_t* ps = (uint32_t*)(smf + 13824);
    float* redmax = smf + 18432;
    float* rowsum = smf + 18560;

    const int tid  = threadIdx.x;
    const int lane = tid & 31;
    const int w    = tid >> 5;
    const int wm   = w >> 1;    // 0..1 -> 32 q-rows each
    const int wn   = w & 1;     // 0..1 -> 32 cols each
    const int lr   = lane >> 2;
    const int lc   = lane & 3;

    const int bh = blockIdx.y;
    const int b  = bh >> 4;
    const int h  = bh & 15;
    const int q0 = blockIdx.x * 64;
    const float scale = 0.03125f;   // 1/sqrt(1024)

    const int fr = tid >> 4;          // 0..7
    const int fc = (tid & 15) * 4;    // 0..60

    // load Q tile (scale folded in, tf32-converted)
    const float* qbase = Q + ((size_t)(b * SS + q0)) * DD + h * HD;
    #pragma unroll
    for (int i = 0; i < 8; i++) {
        int r = fr + i * 8;
        float4 v = *(const float4*)&qbase[(size_t)r * DD + fc];
        uint4 u = { f2tf32(v.x * scale), f2tf32(v.y * scale),
                    f2tf32(v.z * scale), f2tf32(v.w * scale) };
        *(uint4*)&qs[r * 72 + fc] = u;
    }

    float m_state[2][2], l_state[2][2];
    float acco[2][4][4];
    #pragma unroll
    for (int mf = 0; mf < 2; mf++)
        #pragma unroll
        for (int hh = 0; hh < 2; hh++) {
            m_state[mf][hh] = -INFINITY;
            l_state[mf][hh] = 0.0f;
        }
    #pragma unroll
    for (int mf = 0; mf < 2; mf++)
        #pragma unroll
        for (int nf = 0; nf < 4; nf++)
            #pragma unroll
            for (int t = 0; t < 4; t++) acco[mf][nf][t] = 0.0f;

    __syncthreads();

    for (int kb = 0; kb < SS / 64; kb++) {
        // ---- load K,V tiles (tf32) ----
        const float* kbase = Kp + ((size_t)(b * SS + kb * 64)) * DD + h * HD;
        const float* vbase = Vp + ((size_t)(b * SS + kb * 64)) * DD + h * HD;
        #pragma unroll
        for (int i = 0; i < 8; i++) {
            int r = fr + i * 8;
            float4 vk = *(const float4*)&kbase[(size_t)r * DD + fc];
            float4 vv = *(const float4*)&vbase[(size_t)r * DD + fc];
            uint4 uk = { f2tf32(vk.x), f2tf32(vk.y), f2tf32(vk.z), f2tf32(vk.w) };
            uint4 uv = { f2tf32(vv.x), f2tf32(vv.y), f2tf32(vv.z), f2tf32(vv.w) };
            *(uint4*)&ks[r * 72 + fc] = uk;
            *(uint4*)&vs[r * 72 + fc] = uv;
        }
        __syncthreads();                                  // (1)

        // ---- S = Q * K^T (warp tile 32x32) ----
        float accs[2][4][4];
        #pragma unroll
        for (int mf = 0; mf < 2; mf++)
            #pragma unroll
            for (int nf = 0; nf < 4; nf++)
                #pragma unroll
                for (int t = 0; t < 4; t++) accs[mf][nf][t] = 0.0f;

        #pragma unroll
        for (int ksi = 0; ksi < 8; ksi++) {
            const int kk = ksi * 8;
            uint32_t af[2][4];
            #pragma unroll
            for (int mf = 0; mf < 2; mf++) {
                int r = wm * 32 + mf * 16 + lr;
                af[mf][0] = qs[r * 72 + kk + lc];
                af[mf][1] = qs[(r + 8) * 72 + kk + lc];
                af[mf][2] = qs[r * 72 + kk + lc + 4];
                af[mf][3] = qs[(r + 8) * 72 + kk + lc + 4];
            }
            uint32_t bf[4][2];
            #pragma unroll
            for (int nf = 0; nf < 4; nf++) {
                int n = wn * 32 + nf * 8 + lr;
                bf[nf][0] = ks[n * 72 + kk + lc];
                bf[nf][1] = ks[n * 72 + kk + lc + 4];
            }
            #pragma unroll
            for (int mf = 0; mf < 2; mf++)
                #pragma unroll
                for (int nf = 0; nf < 4; nf++)
                    mma_tf32(accs[mf][nf], af[mf], bf[nf]);
        }

        // ---- row max (warp-local then cross-warp via smem) ----
        float rmax[2][2];
        #pragma unroll
        for (int mf = 0; mf < 2; mf++)
            #pragma unroll
            for (int hh = 0; hh < 2; hh++) {
                float v = -INFINITY;
                #pragma unroll
                for (int nf = 0; nf < 4; nf++) {
                    v = fmaxf(v, accs[mf][nf][2 * hh]);
                    v = fmaxf(v, accs[mf][nf][2 * hh + 1]);
                }
                v = fmaxf(v, __shfl_xor_sync(0xffffffffu, v, 1));
                v = fmaxf(v, __shfl_xor_sync(0xffffffffu, v, 2));
                rmax[mf][hh] = v;
            }
        if (lc == 0) {
            #pragma unroll
            for (int mf = 0; mf < 2; mf++)
                #pragma unroll
                for (int hh = 0; hh < 2; hh++) {
                    int row = wm * 32 + mf * 16 + hh * 8 + lr;
                    redmax[row * 2 + wn] = rmax[mf][hh];
                }
        }
        __syncthreads();                                  // (2)

        // ---- new m, correction factor, p = exp(s - m), row sums, stage P ----
        float cc[2][2];
        #pragma unroll
        for (int mf = 0; mf < 2; mf++)
            #pragma unroll
            for (int hh = 0; hh < 2; hh++) {
                int row = wm * 32 + mf * 16 + hh * 8 + lr;
                float mt = fmaxf(redmax[row * 2], redmax[row * 2 + 1]);
                float mnew = fmaxf(m_state[mf][hh], mt);
                cc[mf][hh] = __expf(m_state[mf][hh] - mnew);
                m_state[mf][hh] = mnew;
            }

        float rsum[2][2] = {};
        #pragma unroll
        for (int mf = 0; mf < 2; mf++) {
            #pragma unroll
            for (int nf = 0; nf < 4; nf++) {
                float p0 = __expf(accs[mf][nf][0] - m_state[mf][0]);
                float p1 = __expf(accs[mf][nf][1] - m_state[mf][0]);
                float p2 = __expf(accs[mf][nf][2] - m_state[mf][1]);
                float p3 = __expf(accs[mf][nf][3] - m_state[mf][1]);
                rsum[mf][0] += p0 + p1;
                rsum[mf][1] += p2 + p3;
                int r = wm * 32 + mf * 16 + lr;
                int c = wn * 32 + nf * 8 + 2 * lc;
                uint2 u0 = { f2tf32(p0), f2tf32(p1) };
                uint2 u1 = { f2tf32(p2), f2tf32(p3) };
                *(uint2*)&ps[r * 72 + c] = u0;
                *(uint2*)&ps[(r + 8) * 72 + c] = u1;
            }
        }
        #pragma unroll
        for (int mf = 0; mf < 2; mf++)
            #pragma unroll
            for (int hh = 0; hh < 2; hh++) {
                float v = rsum[mf][hh];
                v += __shfl_xor_sync(0xffffffffu, v, 1);
                v += __shfl_xor_sync(0xffffffffu, v, 2);
                rsum[mf][hh] = v;
            }
        if (lc == 0) {
            #pragma unroll
            for (int mf = 0; mf < 2; mf++)
                #pragma unroll
                for (int hh = 0; hh < 2; hh++) {
                    int row = wm * 32 + mf * 16 + hh * 8 + lr;
                    rowsum[row * 2 + wn] = rsum[mf][hh];
                }
        }
        __syncthreads();                                  // (3)

        #pragma unroll
        for (int mf = 0; mf < 2; mf++)
            #pragma unroll
            for (int hh = 0; hh < 2; hh++) {
                int row = wm * 32 + mf * 16 + hh * 8 + lr;
                l_state[mf][hh] = l_state[mf][hh] * cc[mf][hh]
                                + rowsum[row * 2] + rowsum[row * 2 + 1];
            }

        // rescale O accumulators
        #pragma unroll
        for (int mf = 0; mf < 2; mf++)
            #pragma unroll
            for (int nf = 0; nf < 4; nf++) {
                acco[mf][nf][0] *= cc[mf][0];
                acco[mf][nf][1] *= cc[mf][0];
                acco[mf][nf][2] *= cc[mf][1];
                acco[mf][nf][3] *= cc[mf][1];
            }

        // ---- O += P * V (warp tile 32 q x 32 hd, k = 64 keys) ----
        #pragma unroll
        for (int ksi = 0; ksi < 8; ksi++) {
            const int kk = ksi * 8;
            uint32_t af[2][4];
            #pragma unroll
            for (int mf = 0; mf < 2; mf++) {
                int r = wm * 32 + mf * 16 + lr;
                af[mf][0] = ps[r * 72 + kk + lc];
                af[mf][1] = ps[(r + 8) * 72 + kk + lc];
                af[mf][2] = ps[r * 72 + kk + lc + 4];
                af[mf][3] = ps[(r + 8) * 72 + kk + lc + 4];
            }
            uint32_t bf[4][2];
            #pragma unroll
            for (int nf = 0; nf < 4; nf++) {
                int n = wn * 32 + nf * 8 + lr;
                bf[nf][0] = vs[(kk + lc) * 72 + n];
                bf[nf][1] = vs[(kk + lc + 4) * 72 + n];
            }
            #pragma unroll
            for (int mf = 0; mf < 2; mf++)
                #pragma unroll
                for (int nf = 0; nf < 4; nf++)
                    mma_tf32(acco[mf][nf], af[mf], bf[nf]);
        }
        __syncthreads();                                  // (4)
    }

    // ---- epilogue: normalize, write (B,S,D) ----
    float* obase = O + ((size_t)(b * SS + q0)) * DD + h * HD;
    #pragma unroll
    for (int mf = 0; mf < 2; mf++) {
        float inv0 = 1.0f / l_state[mf][0];
        float inv1 = 1.0f / l_state[mf][1];
        int r = wm * 32 + mf * 16 + lr;
        #pragma unroll
        for (int nf = 0; nf < 4; nf++) {
            int c = wn * 32 + nf * 8 + 2 * lc;
            float2 v0 = { acco[mf][nf][0] * inv0, acco[mf][nf][1] * inv0 };
            float2 v1 = { acco[mf][nf][2] * inv1, acco[mf][nf][3] * inv1 };
            *(float2*)&obase[(size_t)r * DD + c] = v0;
            *(float2*)&obase[(size_t)(r + 8) * DD + c] = v1;
        }
    }
}

// ======================================================================
// launch
// ======================================================================
extern "C" void kernel_launch(void* const* d_in, const int* in_sizes, int n_in,
                              void* d_out, int out_size)
{
    const float* queries = (const float*)d_in[0];
    const float* keys    = (const float*)d_in[1];
    const float* values  = (const float*)d_in[2];
    const float* Wq      = (const float*)d_in[3];
    const float* Wk      = (const float*)d_in[4];
    const float* Wv      = (const float*)d_in[5];
    const float* Wo      = (const float*)d_in[6];
    const float* bo      = (const float*)d_in[7];
    float* out = (float*)d_out;

    float *gQ, *gK, *gV, *gA;
    cudaGetSymbolAddress((void**)&gQ, g_Q);
    cudaGetSymbolAddress((void**)&gK, g_K);
    cudaGetSymbolAddress((void**)&gV, g_V);
    cudaGetSymbolAddress((void**)&gA, g_att);

    cudaFuncSetAttribute(flash_tf32_kernel,
                         cudaFuncAttributeMaxDynamicSharedMemorySize,
                         FL_SMEM_BYTES);

    const int M = BB * SS;   // 4096
    const int N = DD;        // 1024
    const int K = DD;        // 1024
    dim3 gemm_grid(N / 128, M / 128);   // (8, 32)
    dim3 gemm_block(256);

    gemm_tf32_kernel<<<gemm_grid, gemm_block>>>(queries, Wq, nullptr, gQ, M, N, K);
    gemm_tf32_kernel<<<gemm_grid, gemm_block>>>(keys,    Wk, nullptr, gK, M, N, K);
    gemm_tf32_kernel<<<gemm_grid, gemm_block>>>(values,  Wv, nullptr, gV, M, N, K);

    dim3 fl_grid(SS / 64, BB * HH);     // (32, 32)
    flash_tf32_kernel<<<fl_grid, 128, FL_SMEM_BYTES>>>(gQ, gK, gV, gA);

    gemm_tf32_kernel<<<gemm_grid, gemm_block>>>(gA, Wo, bo, out, M, N, K);
}

// round 5
// speedup vs baseline: 6.6191x; 1.1647x over previous
#include <cuda_runtime.h>
#include <math.h>
#include <stdint.h>

#define BB 2
#define SS 2048
#define DD 1024
#define HH 16
#define HD 64

// -------- scratch (allocation-free: __device__ globals) --------
__device__ float g_Q[BB*SS*DD];
__device__ float g_K[BB*SS*DD];
__device__ float g_V[BB*SS*DD];
__device__ float g_att[BB*SS*DD];

// -------- helpers --------
__device__ __forceinline__ uint32_t f2tf32(float x) {
    uint32_t r;
    asm("cvt.rna.tf32.f32 %0, %1;" : "=r"(r) : "f"(x));
    return r;
}

__device__ __forceinline__ void mma_tf32(float* d, const uint32_t* a, const uint32_t* b) {
    asm volatile(
        "mma.sync.aligned.m16n8k8.row.col.f32.tf32.tf32.f32 "
        "{%0,%1,%2,%3},{%4,%5,%6,%7},{%8,%9},{%0,%1,%2,%3};"
        : "+f"(d[0]), "+f"(d[1]), "+f"(d[2]), "+f"(d[3])
        : "r"(a[0]), "r"(a[1]), "r"(a[2]), "r"(a[3]), "r"(b[0]), "r"(b[1]));
}

__device__ __forceinline__ void cp_async16(uint32_t smem_addr, const void* gptr) {
    asm volatile("cp.async.cg.shared.global [%0], [%1], 16;"
                 :: "r"(smem_addr), "l"(gptr));
}
__device__ __forceinline__ void cp_commit() {
    asm volatile("cp.async.commit_group;");
}
template <int N>
__device__ __forceinline__ void cp_wait() {
    asm volatile("cp.async.wait_group %0;" :: "n"(N));
}

// ======================================================================
// GEMM: C[M,N] = A[M,K] * B[N,K]^T (+ bias), tf32 tensor core
// block 128M x 256N, 256 threads (8 warps, 2Mx4N), warp tile 64x64, KT=32
// cp.async double-buffered smem (raw fp32), cvt at fragment load.
// smem: As 2x128x36, Bs 2x256x36 floats -> 110,592 B
// ======================================================================
#define G_SMEM_BYTES ((2*128*36 + 2*256*36) * 4)

__global__ __launch_bounds__(256) void gemm_tf32_v2(
    const float* __restrict__ A, const float* __restrict__ Bw,
    const float* __restrict__ bias, float* __restrict__ C,
    int M, int N, int K)
{
    extern __shared__ float gsm[];
    float* As = gsm;                 // [2][128*36]
    float* Bs = gsm + 2 * 128 * 36;  // [2][256*36]

    const int tid  = threadIdx.x;
    const int lane = tid & 31;
    const int w    = tid >> 5;
    const int wm   = w & 1;        // 0..1 -> 64 rows
    const int wn   = w >> 1;       // 0..3 -> 64 cols
    const int lr   = lane >> 2;
    const int lc   = lane & 3;

    const int m0 = blockIdx.y * 128;
    const int n0 = blockIdx.x * 256;

    const uint32_t as_base = (uint32_t)__cvta_generic_to_shared(As);
    const uint32_t bs_base = (uint32_t)__cvta_generic_to_shared(Bs);

    // stage loader: A 128x32 (1024 x 16B chunks), B 256x32 (2048 chunks)
    auto load_stage = [&](int s, int kt) {
        #pragma unroll
        for (int i = 0; i < 4; i++) {
            int id = tid + i * 256;
            int r = id >> 3, c = (id & 7) * 4;
            cp_async16(as_base + (s * 128 * 36 + r * 36 + c) * 4,
                       &A[(size_t)(m0 + r) * K + kt + c]);
        }
        #pragma unroll
        for (int i = 0; i < 8; i++) {
            int id = tid + i * 256;
            int r = id >> 3, c = (id & 7) * 4;
            cp_async16(bs_base + (s * 256 * 36 + r * 36 + c) * 4,
                       &Bw[(size_t)(n0 + r) * K + kt + c]);
        }
        cp_commit();
    };

    float acc[4][8][4];
    #pragma unroll
    for (int i = 0; i < 4; i++)
        #pragma unroll
        for (int j = 0; j < 8; j++)
            #pragma unroll
            for (int t = 0; t < 4; t++) acc[i][j][t] = 0.0f;

    load_stage(0, 0);

    int st = 0;
    for (int kt = 0; kt < K; kt += 32, st ^= 1) {
        if (kt + 32 < K) { load_stage(st ^ 1, kt + 32); cp_wait<1>(); }
        else             { cp_wait<0>(); }
        __syncthreads();

        const float* Ac = As + st * 128 * 36;
        const float* Bc = Bs + st * 256 * 36;

        #pragma unroll
        for (int ks = 0; ks < 4; ks++) {
            const int kk = ks * 8;
            uint32_t af[4][4];
            #pragma unroll
            for (int mf = 0; mf < 4; mf++) {
                int r = wm * 64 + mf * 16 + lr;
                af[mf][0] = f2tf32(Ac[r * 36 + kk + lc]);
                af[mf][1] = f2tf32(Ac[(r + 8) * 36 + kk + lc]);
                af[mf][2] = f2tf32(Ac[r * 36 + kk + lc + 4]);
                af[mf][3] = f2tf32(Ac[(r + 8) * 36 + kk + lc + 4]);
            }
            uint32_t bf[8][2];
            #pragma unroll
            for (int nf = 0; nf < 8; nf++) {
                int n = wn * 64 + nf * 8 + lr;
                bf[nf][0] = f2tf32(Bc[n * 36 + kk + lc]);
                bf[nf][1] = f2tf32(Bc[n * 36 + kk + lc + 4]);
            }
            #pragma unroll
            for (int mf = 0; mf < 4; mf++)
                #pragma unroll
                for (int nf = 0; nf < 8; nf++)
                    mma_tf32(acc[mf][nf], af[mf], bf[nf]);
        }
        __syncthreads();
    }

    #pragma unroll
    for (int mf = 0; mf < 4; mf++) {
        int r = m0 + wm * 64 + mf * 16 + lr;
        #pragma unroll
        for (int nf = 0; nf < 8; nf++) {
            int c = n0 + wn * 64 + nf * 8 + 2 * lc;
            float b0 = 0.0f, b1 = 0.0f;
            if (bias) { b0 = bias[c]; b1 = bias[c + 1]; }
            float2 v0 = { acc[mf][nf][0] + b0, acc[mf][nf][1] + b1 };
            float2 v1 = { acc[mf][nf][2] + b0, acc[mf][nf][3] + b1 };
            *(float2*)&C[(size_t)r * N + c] = v0;
            *(float2*)&C[(size_t)(r + 8) * N + c] = v1;
        }
    }
}

// ======================================================================
// Flash attention v2, tf32. 128-row q tile, 4 warps, warp = 32 q x 64 keys.
// Softmax fully warp-local (rows exclusive to one warp). 2 syncs/tile.
// smem (floats, stride 72): qs 128x72 @0, ks 64x72 @9216, vs @13824,
//                           ps 128x72 @18432 -> 27648 floats = 110,592 B
// ======================================================================
#define FL_SMEM_BYTES (27648 * 4)

__global__ __launch_bounds__(128) void flash_tf32_v2(
    const float* __restrict__ Q, const float* __restrict__ Kp,
    const float* __restrict__ Vp, float* __restrict__ O)
{
    extern __shared__ float smf[];
    uint32_t* qs = (uint32_t*)smf;
    uint32_t* ks = (uint32_t*)(smf + 9216);
    uint32_t* vs = (uint32_t*)(smf + 13824);
    uint32_t* ps = (uint32_t*)(smf + 18432);

    const int tid  = threadIdx.x;
    const int lane = tid & 31;
    const int w    = tid >> 5;      // 0..3: 32 q-rows each
    const int lr   = lane >> 2;
    const int lc   = lane & 3;

    const int bh = blockIdx.y;
    const int b  = bh >> 4;
    const int h  = bh & 15;
    const int q0 = blockIdx.x * 128;
    const float scale = 0.03125f;   // 1/sqrt(1024)

    const int fr = tid >> 4;          // 0..7
    const int fc = (tid & 15) * 4;    // 0..60

    // ---- load Q tile (128 x 64), scale folded, tf32 ----
    const float* qbase = Q + ((size_t)(b * SS + q0)) * DD + h * HD;
    #pragma unroll
    for (int i = 0; i < 16; i++) {
        int r = fr + i * 8;
        float4 v = *(const float4*)&qbase[(size_t)r * DD + fc];
        uint4 u = { f2tf32(v.x * scale), f2tf32(v.y * scale),
                    f2tf32(v.z * scale), f2tf32(v.w * scale) };
        *(uint4*)&qs[r * 72 + fc] = u;
    }

    float m_state[2][2], l_state[2][2];
    float acco[2][8][4];
    #pragma unroll
    for (int mf = 0; mf < 2; mf++)
        #pragma unroll
        for (int hh = 0; hh < 2; hh++) { m_state[mf][hh] = -INFINITY; l_state[mf][hh] = 0.0f; }
    #pragma unroll
    for (int mf = 0; mf < 2; mf++)
        #pragma unroll
        for (int nf = 0; nf < 8; nf++)
            #pragma unroll
            for (int t = 0; t < 4; t++) acco[mf][nf][t] = 0.0f;

    // prefetch K/V tile 0 into regs
    const float* kb0 = Kp + ((size_t)(b * SS)) * DD + h * HD;
    const float* vb0 = Vp + ((size_t)(b * SS)) * DD + h * HD;
    float4 kreg[8], vreg[8];
    #pragma unroll
    for (int i = 0; i < 8; i++) {
        int r = fr + i * 8;
        kreg[i] = *(const float4*)&kb0[(size_t)r * DD + fc];
        vreg[i] = *(const float4*)&vb0[(size_t)r * DD + fc];
    }

    for (int kb = 0; kb < SS / 64; kb++) {
        __syncthreads();   // previous tile fully consumed
        #pragma unroll
        for (int i = 0; i < 8; i++) {
            int r = fr + i * 8;
            uint4 uk = { f2tf32(kreg[i].x), f2tf32(kreg[i].y), f2tf32(kreg[i].z), f2tf32(kreg[i].w) };
            uint4 uv = { f2tf32(vreg[i].x), f2tf32(vreg[i].y), f2tf32(vreg[i].z), f2tf32(vreg[i].w) };
            *(uint4*)&ks[r * 72 + fc] = uk;
            *(uint4*)&vs[r * 72 + fc] = uv;
        }
        __syncthreads();   // tile visible

        // prefetch next tile (overlaps compute)
        if (kb + 1 < SS / 64) {
            const float* kbn = Kp + ((size_t)(b * SS + (kb + 1) * 64)) * DD + h * HD;
            const float* vbn = Vp + ((size_t)(b * SS + (kb + 1) * 64)) * DD + h * HD;
            #pragma unroll
            for (int i = 0; i < 8; i++) {
                int r = fr + i * 8;
                kreg[i] = *(const float4*)&kbn[(size_t)r * DD + fc];
                vreg[i] = *(const float4*)&vbn[(size_t)r * DD + fc];
            }
        }

        // ---- S = Q K^T : warp tile 32 q x 64 keys ----
        float accs[2][8][4];
        #pragma unroll
        for (int mf = 0; mf < 2; mf++)
            #pragma unroll
            for (int nf = 0; nf < 8; nf++)
                #pragma unroll
                for (int t = 0; t < 4; t++) accs[mf][nf][t] = 0.0f;

        #pragma unroll
        for (int ksi = 0; ksi < 8; ksi++) {
            const int kk = ksi * 8;
            uint32_t af[2][4];
            #pragma unroll
            for (int mf = 0; mf < 2; mf++) {
                int r = w * 32 + mf * 16 + lr;
                af[mf][0] = qs[r * 72 + kk + lc];
                af[mf][1] = qs[(r + 8) * 72 + kk + lc];
                af[mf][2] = qs[r * 72 + kk + lc + 4];
                af[mf][3] = qs[(r + 8) * 72 + kk + lc + 4];
            }
            uint32_t bf[8][2];
            #pragma unroll
            for (int nf = 0; nf < 8; nf++) {
                int n = nf * 8 + lr;
                bf[nf][0] = ks[n * 72 + kk + lc];
                bf[nf][1] = ks[n * 72 + kk + lc + 4];
            }
            #pragma unroll
            for (int mf = 0; mf < 2; mf++)
                #pragma unroll
                for (int nf = 0; nf < 8; nf++)
                    mma_tf32(accs[mf][nf], af[mf], bf[nf]);
        }

        // ---- warp-local online softmax ----
        float cc[2][2];
        #pragma unroll
        for (int mf = 0; mf < 2; mf++)
            #pragma unroll
            for (int hh = 0; hh < 2; hh++) {
                float v = -INFINITY;
                #pragma unroll
                for (int nf = 0; nf < 8; nf++) {
                    v = fmaxf(v, accs[mf][nf][2 * hh]);
                    v = fmaxf(v, accs[mf][nf][2 * hh + 1]);
                }
                v = fmaxf(v, __shfl_xor_sync(0xffffffffu, v, 1));
                v = fmaxf(v, __shfl_xor_sync(0xffffffffu, v, 2));
                float mnew = fmaxf(m_state[mf][hh], v);
                cc[mf][hh] = __expf(m_state[mf][hh] - mnew);
                m_state[mf][hh] = mnew;
            }

        float rsum[2][2] = {};
        #pragma unroll
        for (int mf = 0; mf < 2; mf++) {
            #pragma unroll
            for (int nf = 0; nf < 8; nf++) {
                float p0 = __expf(accs[mf][nf][0] - m_state[mf][0]);
                float p1 = __expf(accs[mf][nf][1] - m_state[mf][0]);
                float p2 = __expf(accs[mf][nf][2] - m_state[mf][1]);
                float p3 = __expf(accs[mf][nf][3] - m_state[mf][1]);
                rsum[mf][0] += p0 + p1;
                rsum[mf][1] += p2 + p3;
                int r = w * 32 + mf * 16 + lr;
                int c = nf * 8 + 2 * lc;
                uint2 u0 = { f2tf32(p0), f2tf32(p1) };
                uint2 u1 = { f2tf32(p2), f2tf32(p3) };
                *(uint2*)&ps[r * 72 + c] = u0;
                *(uint2*)&ps[(r + 8) * 72 + c] = u1;
            }
        }
        #pragma unroll
        for (int mf = 0; mf < 2; mf++)
            #pragma unroll
            for (int hh = 0; hh < 2; hh++) {
                float v = rsum[mf][hh];
                v += __shfl_xor_sync(0xffffffffu, v, 1);
                v += __shfl_xor_sync(0xffffffffu, v, 2);
                l_state[mf][hh] = l_state[mf][hh] * cc[mf][hh] + v;
            }

        // rescale O accumulators
        #pragma unroll
        for (int mf = 0; mf < 2; mf++)
            #pragma unroll
            for (int nf = 0; nf < 8; nf++) {
                acco[mf][nf][0] *= cc[mf][0];
                acco[mf][nf][1] *= cc[mf][0];
                acco[mf][nf][2] *= cc[mf][1];
                acco[mf][nf][3] *= cc[mf][1];
            }

        __syncwarp();   // order P stores before P fragment loads (warp-private rows)

        // ---- O += P V : warp tile 32 q x 64 dims, k = 64 keys ----
        #pragma unroll
        for (int ksi = 0; ksi < 8; ksi++) {
            const int kk = ksi * 8;
            uint32_t af[2][4];
            #pragma unroll
            for (int mf = 0; mf < 2; mf++) {
                int r = w * 32 + mf * 16 + lr;
                af[mf][0] = ps[r * 72 + kk + lc];
                af[mf][1] = ps[(r + 8) * 72 + kk + lc];
                af[mf][2] = ps[r * 72 + kk + lc + 4];
                af[mf][3] = ps[(r + 8) * 72 + kk + lc + 4];
            }
            uint32_t bf[8][2];
            #pragma unroll
            for (int nf = 0; nf < 8; nf++) {
                int n = nf * 8 + lr;
                bf[nf][0] = vs[(kk + lc) * 72 + n];
                bf[nf][1] = vs[(kk + lc + 4) * 72 + n];
            }
            #pragma unroll
            for (int mf = 0; mf < 2; mf++)
                #pragma unroll
                for (int nf = 0; nf < 8; nf++)
                    mma_tf32(acco[mf][nf], af[mf], bf[nf]);
        }
    }

    // ---- epilogue ----
    float* obase = O + ((size_t)(b * SS + q0)) * DD + h * HD;
    #pragma unroll
    for (int mf = 0; mf < 2; mf++) {
        float inv0 = 1.0f / l_state[mf][0];
        float inv1 = 1.0f / l_state[mf][1];
        int r = w * 32 + mf * 16 + lr;
        #pragma unroll
        for (int nf = 0; nf < 8; nf++) {
            int c = nf * 8 + 2 * lc;
            float2 v0 = { acco[mf][nf][0] * inv0, acco[mf][nf][1] * inv0 };
            float2 v1 = { acco[mf][nf][2] * inv1, acco[mf][nf][3] * inv1 };
            *(float2*)&obase[(size_t)r * DD + c] = v0;
            *(float2*)&obase[(size_t)(r + 8) * DD + c] = v1;
        }
    }
}

// ======================================================================
// launch
// ======================================================================
extern "C" void kernel_launch(void* const* d_in, const int* in_sizes, int n_in,
                              void* d_out, int out_size)
{
    const float* queries = (const float*)d_in[0];
    const float* keys    = (const float*)d_in[1];
    const float* values  = (const float*)d_in[2];
    const float* Wq      = (const float*)d_in[3];
    const float* Wk      = (const float*)d_in[4];
    const float* Wv      = (const float*)d_in[5];
    const float* Wo      = (const float*)d_in[6];
    const float* bo      = (const float*)d_in[7];
    float* out = (float*)d_out;

    float *gQ, *gK, *gV, *gA;
    cudaGetSymbolAddress((void**)&gQ, g_Q);
    cudaGetSymbolAddress((void**)&gK, g_K);
    cudaGetSymbolAddress((void**)&gV, g_V);
    cudaGetSymbolAddress((void**)&gA, g_att);

    cudaFuncSetAttribute(gemm_tf32_v2,
                         cudaFuncAttributeMaxDynamicSharedMemorySize, G_SMEM_BYTES);
    cudaFuncSetAttribute(flash_tf32_v2,
                         cudaFuncAttributeMaxDynamicSharedMemorySize, FL_SMEM_BYTES);

    const int M = BB * SS;   // 4096
    const int N = DD;        // 1024
    const int K = DD;        // 1024
    dim3 gemm_grid(N / 256, M / 128);   // (4, 32) = 128 blocks
    dim3 gemm_block(256);

    gemm_tf32_v2<<<gemm_grid, gemm_block, G_SMEM_BYTES>>>(queries, Wq, nullptr, gQ, M, N, K);
    gemm_tf32_v2<<<gemm_grid, gemm_block, G_SMEM_BYTES>>>(keys,    Wk, nullptr, gK, M, N, K);
    gemm_tf32_v2<<<gemm_grid, gemm_block, G_SMEM_BYTES>>>(values,  Wv, nullptr, gV, M, N, K);

    dim3 fl_grid(SS / 128, BB * HH);    // (16, 32) = 512 blocks
    flash_tf32_v2<<<fl_grid, 128, FL_SMEM_BYTES>>>(gQ, gK, gV, gA);

    gemm_tf32_v2<<<gemm_grid, gemm_block, G_SMEM_BYTES>>>(gA, Wo, bo, out, M, N, K);
}